// round 6
// baseline (speedup 1.0000x reference)
#include <cuda_runtime.h>
#include <cuda_bf16.h>
#include <math.h>
#include <stdint.h>

#define NN 50000
#define NE 300000
#define HID 256
#define NLAYER 4
#define NG 1024
#define NODE_DIM 11
#define EDGE_DIM 5
#define NSB ((NN + 255) / 256)    // 196 scan blocks
#define NMB ((NN + 127) / 128)    // 391 GEMM M-blocks

// ---------------- persistent scratch (device globals; no allocation) ----------------
__device__ __align__(16) float d_h[NN * HID];
__device__ __align__(16) float d_z[NN * HID];            // GEMM2 out (fp32, for BN)
__device__ __align__(16) __nv_bfloat16 d_zhi[NN * HID];  // GEMM1 input hi
__device__ __align__(16) __nv_bfloat16 d_zlo[NN * HID];
__device__ __align__(16) __nv_bfloat16 d_thi[NN * HID];  // GEMM2 input hi
__device__ __align__(16) __nv_bfloat16 d_tlo[NN * HID];
__device__ __align__(16) __nv_bfloat16 d_Wc[NLAYER * 2 * 2 * HID * HID]; // [l][mat][hl][n][k]
__device__ int   d_cnt[NN];
__device__ int   d_rowptr[NN + 1];
__device__ int   d_eids[NE];
__device__ int   d_bsums[NSB];
__device__ int   d_boff[NSB];
__device__ float d_psum[NMB * HID];
__device__ float d_psq[NMB * HID];
__device__ float d_scale[HID];
__device__ float d_shift[HID];
__device__ int   d_gstart[NG + 1];
__device__ float d_gfeat[NG * 3 * HID];
__device__ float d_h1[NG * HID];
__device__ float d_h2[NG * (HID / 2)];

// ================= portable PTX helpers (sm_80+ baseline; NO tcgen05) =================
__device__ __forceinline__ uint32_t smem_u32(const void* p) {
    uint32_t a;
    asm("{ .reg .u64 t; cvta.to.shared.u64 t, %1; cvt.u32.u64 %0, t; }" : "=r"(a) : "l"(p));
    return a;
}
#define SW128(x) ((x) ^ (((x) >> 3) & 0x70))

__device__ __forceinline__ void cp16(uint32_t dst, const void* src, int srcbytes) {
    asm volatile("cp.async.cg.shared.global [%0], [%1], 16, %2;"
                 :: "r"(dst), "l"(src), "r"(srcbytes) : "memory");
}
#define CP_COMMIT() asm volatile("cp.async.commit_group;" ::: "memory")
#define CP_WAIT0()  asm volatile("cp.async.wait_group 0;" ::: "memory")
#define CP_WAIT1()  asm volatile("cp.async.wait_group 1;" ::: "memory")

__device__ __forceinline__ void ldsm4(uint32_t* r, uint32_t addr) {
    asm volatile("ldmatrix.sync.aligned.m8n8.x4.shared.b16 {%0,%1,%2,%3}, [%4];"
                 : "=r"(r[0]), "=r"(r[1]), "=r"(r[2]), "=r"(r[3]) : "r"(addr));
}
__device__ __forceinline__ void mma16816(float* c, const uint32_t* a, const uint32_t* b) {
    asm volatile("mma.sync.aligned.m16n8k16.row.col.f32.bf16.bf16.f32 "
                 "{%0,%1,%2,%3}, {%4,%5,%6,%7}, {%8,%9}, {%0,%1,%2,%3};"
                 : "+f"(c[0]), "+f"(c[1]), "+f"(c[2]), "+f"(c[3])
                 : "r"(a[0]), "r"(a[1]), "r"(a[2]), "r"(a[3]), "r"(b[0]), "r"(b[1]));
}

// ---------------- CSR build ----------------
__global__ void k_zero_cnt() {
    int i = blockIdx.x * blockDim.x + threadIdx.x;
    if (i < NN) d_cnt[i] = 0;
}
__global__ void k_count(const int* __restrict__ ei) {
    int e = blockIdx.x * blockDim.x + threadIdx.x;
    if (e < NE) atomicAdd(&d_cnt[ei[NE + e]], 1);
}
__global__ void k_bsum() {
    __shared__ int red[256];
    int tid = threadIdx.x;
    int i = blockIdx.x * 256 + tid;
    red[tid] = (i < NN) ? d_cnt[i] : 0;
    __syncthreads();
    for (int off = 128; off; off >>= 1) {
        if (tid < off) red[tid] += red[tid + off];
        __syncthreads();
    }
    if (tid == 0) d_bsums[blockIdx.x] = red[0];
}
__global__ void k_bscan() {
    __shared__ int buf[256];
    int tid = threadIdx.x;
    int v = (tid < NSB) ? d_bsums[tid] : 0;
    buf[tid] = v;
    __syncthreads();
    for (int off = 1; off < 256; off <<= 1) {
        int t = (tid >= off) ? buf[tid - off] : 0;
        __syncthreads();
        buf[tid] += t;
        __syncthreads();
    }
    if (tid < NSB) d_boff[tid] = buf[tid] - v;   // exclusive
    if (tid == 0) d_rowptr[NN] = NE;
}
__global__ void k_badd() {
    __shared__ int buf[256];
    int tid = threadIdx.x;
    int i = blockIdx.x * 256 + tid;
    int v = (i < NN) ? d_cnt[i] : 0;
    buf[tid] = v;
    __syncthreads();
    for (int off = 1; off < 256; off <<= 1) {
        int t = (tid >= off) ? buf[tid - off] : 0;
        __syncthreads();
        buf[tid] += t;
        __syncthreads();
    }
    if (i < NN) {
        int excl = buf[tid] - v + d_boff[blockIdx.x];
        d_rowptr[i] = excl;
        d_cnt[i] = excl;   // scatter cursor
    }
}
__global__ void k_scatter(const int* __restrict__ ei) {
    int e = blockIdx.x * blockDim.x + threadIdx.x;
    if (e < NE) {
        int pos = atomicAdd(&d_cnt[ei[NE + e]], 1);
        d_eids[pos] = e;
    }
}
__global__ void k_sortrows() {
    int i = blockIdx.x * blockDim.x + threadIdx.x;
    if (i >= NN) return;
    int rs = d_rowptr[i], re = d_rowptr[i + 1];
    for (int a = rs + 1; a < re; a++) {
        int key = d_eids[a];
        int b = a - 1;
        while (b >= rs && d_eids[b] > key) { d_eids[b + 1] = d_eids[b]; b--; }
        d_eids[b + 1] = key;
    }
}

// ---------------- encoder ----------------
#define ENC_NPB 64
__global__ void k_encoder(const float* __restrict__ x, const float* __restrict__ W,
                          const float* __restrict__ b) {
    __shared__ float Ws[NODE_DIM][HID];
    __shared__ float bs[HID];
    int c = threadIdx.x;
    #pragma unroll
    for (int k = 0; k < NODE_DIM; k++) Ws[k][c] = W[k * HID + c];
    bs[c] = b[c];
    __syncthreads();
    int n0 = blockIdx.x * ENC_NPB;
    for (int i = 0; i < ENC_NPB; i++) {
        int n = n0 + i;
        if (n >= NN) break;
        float acc = bs[c];
        #pragma unroll
        for (int k = 0; k < NODE_DIM; k++) acc += __ldg(&x[n * NODE_DIM + k]) * Ws[k][c];
        d_h[n * HID + c] = fmaxf(acc, 0.f);
    }
}

// ---------------- weight conversion: W -> transposed bf16 hi/lo ----------------
__global__ void k_convW(const float* __restrict__ W1, const float* __restrict__ W2) {
    int idx = blockIdx.x * blockDim.x + threadIdx.x;
    if (idx >= NLAYER * 2 * HID * HID) return;
    int e = idx & 65535;
    int lm = idx >> 16;                // l*2 + mat
    int l = lm >> 1, mat = lm & 1;
    int n = e & 255, k = e >> 8;
    const float* W = mat ? W2 : W1;
    float w = W[l * 65536 + k * 256 + n];
    __nv_bfloat16 hi = __float2bfloat16(w);
    __nv_bfloat16 lo = __float2bfloat16(w - __bfloat162float(hi));
    d_Wc[(size_t)(lm * 2 + 0) * 65536 + n * 256 + k] = hi;
    d_Wc[(size_t)(lm * 2 + 1) * 65536 + n * 256 + k] = lo;
}

// ---------------- GINE aggregation ----------------
__global__ void k_aggregate(const int* __restrict__ ei, const float* __restrict__ ea,
                            const float* __restrict__ eW, const float* __restrict__ eb) {
    __shared__ float Ws[EDGE_DIM][HID];
    __shared__ float bs[HID];
    int c = threadIdx.x;
    #pragma unroll
    for (int k = 0; k < EDGE_DIM; k++) Ws[k][c] = eW[k * HID + c];
    bs[c] = eb[c];
    __syncthreads();
    int n0 = blockIdx.x * 8;
    for (int i = 0; i < 8; i++) {
        int n = n0 + i;
        if (n >= NN) break;
        int rs = d_rowptr[n], re = d_rowptr[n + 1];
        float acc = d_h[n * HID + c];
        for (int p = rs; p < re; p++) {
            int e = d_eids[p];
            int src = ei[e];
            float ec = bs[c];
            #pragma unroll
            for (int k = 0; k < EDGE_DIM; k++) ec += __ldg(&ea[e * EDGE_DIM + k]) * Ws[k][c];
            acc += fmaxf(d_h[src * HID + c] + ec, 0.f);
        }
        __nv_bfloat16 hi = __float2bfloat16(acc);
        d_zhi[n * HID + c] = hi;
        d_zlo[n * HID + c] = __float2bfloat16(acc - __bfloat162float(hi));
    }
}

// ---------------- HMMA GEMM: D[M,256] = (Ahi+Alo)[M,256] @ (Whi+Wlo)^T + bias ----------------
// Virtual K = 768: term 0 = Ah*Wh, term 1 = Ah*Wl, term 2 = Al*Wh.
// CTA tile 128(M) x 256(N, full); 8 warps = 2(M) x 4(N); warp tile 64x64; k-chunk 64, double-buffered.
// MODE 0: out = relu(D+bias) split -> (Ohi, Olo). MODE 1: out = D+bias -> Of (fp32) + BN partial stats.
#define SM_A_BYTES 16384               // 128 rows x 64k x 2B
#define SM_B_BYTES 32768               // 256 rows x 64k x 2B
#define SM_BUF (SM_A_BYTES + SM_B_BYTES)   // 48KB per buffer
#define SM_TOT (2 * SM_BUF)                // 96KB

__device__ __forceinline__ void g_load_chunk(
    uint32_t sb, int buf, int vk, int tid, int bm,
    const __nv_bfloat16* __restrict__ Ahi, const __nv_bfloat16* __restrict__ Alo,
    const __nv_bfloat16* __restrict__ Wc) {
    int term = vk >> 8, kk = vk & 255;
    const __nv_bfloat16* Asrc = (term == 2) ? Alo : Ahi;
    const __nv_bfloat16* Bsrc = Wc + ((term == 1) ? 65536 : 0);
    uint32_t abase = sb + buf * SM_BUF;
    uint32_t bbase = abase + SM_A_BYTES;
    #pragma unroll
    for (int t = 0; t < 4; t++) {
        int idx = tid + t * 256;
        int row = idx >> 3, seg = idx & 7;
        int gm = bm + row;
        cp16(abase + SW128(row * 128 + seg * 16),
             Asrc + (size_t)gm * 256 + kk + seg * 8, (gm < NN) ? 16 : 0);
    }
    #pragma unroll
    for (int t = 0; t < 8; t++) {
        int idx = tid + t * 256;
        int row = idx >> 3, seg = idx & 7;   // row = n in [0,256)
        cp16(bbase + SW128(row * 128 + seg * 16),
             Bsrc + (size_t)row * 256 + kk + seg * 8, 16);
    }
    CP_COMMIT();
}

template <int MODE>
__global__ __launch_bounds__(256, 1)
void k_mma_gemm(const __nv_bfloat16* __restrict__ Ahi, const __nv_bfloat16* __restrict__ Alo,
                const __nv_bfloat16* __restrict__ Wc,   // [2 hl][256 n][256 k] bf16
                const float* __restrict__ bias,
                __nv_bfloat16* __restrict__ Ohi, __nv_bfloat16* __restrict__ Olo,
                float* __restrict__ Of) {
    extern __shared__ char smem[];
    uint32_t sb = smem_u32(smem);
    int tid = threadIdx.x, wid = tid >> 5, lane = tid & 31;
    int bm = blockIdx.x * 128;
    int wm = wid & 1, wn = wid >> 1;   // warp tile: rows wm*64, cols wn*64

    float c[4][8][4];
    #pragma unroll
    for (int mt = 0; mt < 4; mt++)
        #pragma unroll
        for (int nt = 0; nt < 8; nt++)
            #pragma unroll
            for (int q = 0; q < 4; q++) c[mt][nt][q] = 0.f;

    g_load_chunk(sb, 0, 0, tid, bm, Ahi, Alo, Wc);

    #pragma unroll 1
    for (int i = 0; i < 12; i++) {
        if (i + 1 < 12) {
            g_load_chunk(sb, (i + 1) & 1, (i + 1) * 64, tid, bm, Ahi, Alo, Wc);
            CP_WAIT1();
        } else {
            CP_WAIT0();
        }
        __syncthreads();
        uint32_t abase = sb + (i & 1) * SM_BUF;
        uint32_t bbase = abase + SM_A_BYTES;
        #pragma unroll
        for (int ks = 0; ks < 4; ks++) {
            uint32_t a[4][4], b[8][2];
            #pragma unroll
            for (int mt = 0; mt < 4; mt++) {
                int row = wm * 64 + mt * 16 + (lane & 15);
                ldsm4(a[mt], abase + SW128(row * 128 + ks * 32 + (lane >> 4) * 16));
            }
            #pragma unroll
            for (int p = 0; p < 4; p++) {   // each ldsm4: two 8-col n-tiles x two k-halves
                uint32_t r4[4];
                int row = wn * 64 + (p * 2 + (lane >> 4)) * 8 + (lane & 7);
                ldsm4(r4, bbase + SW128(row * 128 + ks * 32 + ((lane >> 3) & 1) * 16));
                b[2 * p + 0][0] = r4[0]; b[2 * p + 0][1] = r4[1];
                b[2 * p + 1][0] = r4[2]; b[2 * p + 1][1] = r4[3];
            }
            #pragma unroll
            for (int mt = 0; mt < 4; mt++)
                #pragma unroll
                for (int nt = 0; nt < 8; nt++)
                    mma16816(c[mt][nt], a[mt], b[nt]);
        }
        __syncthreads();
    }

    // epilogue
    int gid = lane >> 2, tig = lane & 3;
    float s[16], s2[16];
    if (MODE == 1) {
        #pragma unroll
        for (int j = 0; j < 16; j++) { s[j] = 0.f; s2[j] = 0.f; }
    }
    #pragma unroll
    for (int mt = 0; mt < 4; mt++) {
        #pragma unroll
        for (int nt = 0; nt < 8; nt++) {
            int col = wn * 64 + nt * 8 + tig * 2;
            float b0 = __ldg(&bias[col]), b1 = __ldg(&bias[col + 1]);
            #pragma unroll
            for (int half = 0; half < 2; half++) {
                int r = bm + wm * 64 + mt * 16 + gid + half * 8;
                if (r >= NN) continue;
                float v0 = c[mt][nt][half * 2 + 0] + b0;
                float v1 = c[mt][nt][half * 2 + 1] + b1;
                if (MODE == 0) {
                    v0 = fmaxf(v0, 0.f); v1 = fmaxf(v1, 0.f);
                    __nv_bfloat16 h0 = __float2bfloat16(v0), h1 = __float2bfloat16(v1);
                    __nv_bfloat16 l0 = __float2bfloat16(v0 - __bfloat162float(h0));
                    __nv_bfloat16 l1 = __float2bfloat16(v1 - __bfloat162float(h1));
                    *(__nv_bfloat162*)(Ohi + (size_t)r * 256 + col) = __halves2bfloat162(h0, h1);
                    *(__nv_bfloat162*)(Olo + (size_t)r * 256 + col) = __halves2bfloat162(l0, l1);
                } else {
                    *(float2*)(Of + (size_t)r * 256 + col) = make_float2(v0, v1);
                    s[nt * 2 + 0] += v0; s2[nt * 2 + 0] += v0 * v0;
                    s[nt * 2 + 1] += v1; s2[nt * 2 + 1] += v1 * v1;
                }
            }
        }
    }
    if (MODE == 1) {
        #pragma unroll
        for (int j = 0; j < 16; j++) {
            #pragma unroll
            for (int off = 4; off < 32; off <<= 1) {
                s[j]  += __shfl_xor_sync(0xffffffffu, s[j], off);
                s2[j] += __shfl_xor_sync(0xffffffffu, s2[j], off);
            }
        }
        float* ss  = (float*)smem;          // [2 wm][256]
        float* ssq = ss + 512;              // [2 wm][256]
        __syncthreads();                    // smem no longer needed by mma loop
        if (gid == 0) {
            #pragma unroll
            for (int nt = 0; nt < 8; nt++) {
                #pragma unroll
                for (int q = 0; q < 2; q++) {
                    int cl = wn * 64 + nt * 8 + tig * 2 + q;
                    ss[wm * 256 + cl]  = s[nt * 2 + q];
                    ssq[wm * 256 + cl] = s2[nt * 2 + q];
                }
            }
        }
        __syncthreads();
        {
            int slot = blockIdx.x * 256 + tid;
            d_psum[slot] = ss[tid] + ss[256 + tid];
            d_psq[slot]  = ssq[tid] + ssq[256 + tid];
        }
    }
}

// ---------------- BatchNorm finalize + apply ----------------
__global__ void k_bn_final(const float* __restrict__ g, const float* __restrict__ b) {
    int c = threadIdx.x;
    float s = 0.f, s2 = 0.f;
    for (int blk = 0; blk < NMB; blk++) {
        s += d_psum[blk * HID + c];
        s2 += d_psq[blk * HID + c];
    }
    float mu = s / (float)NN;
    float var = s2 / (float)NN - mu * mu;
    float sc = g[c] * rsqrtf(var + 1e-5f);
    d_scale[c] = sc;
    d_shift[c] = b[c] - mu * sc;
}
__global__ void k_bn_apply() {
    int idx = blockIdx.x * blockDim.x + threadIdx.x;   // float4 index
    if (idx >= NN * 64) return;
    int c4 = idx & 63;
    float4 z = *(const float4*)(d_z + idx * 4);
    float4 h = *(const float4*)(d_h + idx * 4);
    float4 sc = *(const float4*)(d_scale + c4 * 4);
    float4 sh = *(const float4*)(d_shift + c4 * 4);
    h.x += fmaxf(z.x * sc.x + sh.x, 0.f);
    h.y += fmaxf(z.y * sc.y + sh.y, 0.f);
    h.z += fmaxf(z.z * sc.z + sh.z, 0.f);
    h.w += fmaxf(z.w * sc.w + sh.w, 0.f);
    *(float4*)(d_h + idx * 4) = h;
}

// ---------------- graph pooling (fused with layer-3 BN apply) ----------------
__global__ void k_gbounds(const int* __restrict__ batch) {
    int g = blockIdx.x * blockDim.x + threadIdx.x;
    if (g > NG) return;
    if (g == NG) { d_gstart[NG] = NN; return; }
    int lo = 0, hi = NN;
    while (lo < hi) {
        int mid = (lo + hi) >> 1;
        if (batch[mid] < g) lo = mid + 1; else hi = mid;
    }
    d_gstart[g] = lo;
}
__global__ void k_pool_bn() {
    int g = blockIdx.x, c = threadIdx.x;
    int s0 = d_gstart[g], s1 = d_gstart[g + 1];
    float sc = d_scale[c], sh = d_shift[c];
    float sum = 0.f;
    float mx = -INFINITY;
    for (int n = s0; n < s1; n++) {
        float hn = fmaxf(d_z[n * HID + c] * sc + sh, 0.f) + d_h[n * HID + c];
        sum += hn;
        mx = fmaxf(mx, hn);
    }
    float cntf = (float)(s1 - s0);
    float mean = sum / fmaxf(cntf, 1.f);
    d_gfeat[g * 768 + c] = mean;
    d_gfeat[g * 768 + 256 + c] = sum;
    d_gfeat[g * 768 + 512 + c] = mx;
}

// ---------------- head ----------------
__global__ void k_head1(const float* __restrict__ W, const float* __restrict__ b) {
    __shared__ float gs[8][768];
    int tid = threadIdx.x;
    int g0 = blockIdx.x * 8;
    for (int j = 0; j < 8; j++)
        for (int idx = tid; idx < 768; idx += 256)
            gs[j][idx] = d_gfeat[(g0 + j) * 768 + idx];
    __syncthreads();
    int c = tid;
    float acc[8];
    float bv = b[c];
    #pragma unroll
    for (int j = 0; j < 8; j++) acc[j] = bv;
    for (int k = 0; k < 768; k++) {
        float w = W[k * 256 + c];
        #pragma unroll
        for (int j = 0; j < 8; j++) acc[j] += gs[j][k] * w;
    }
    #pragma unroll
    for (int j = 0; j < 8; j++) d_h1[(g0 + j) * 256 + c] = fmaxf(acc[j], 0.f);
}
__global__ void k_head2(const float* __restrict__ W, const float* __restrict__ b) {
    __shared__ float hs[8][256];
    int tid = threadIdx.x;  // 128 threads
    int g0 = blockIdx.x * 8;
    for (int j = 0; j < 8; j++)
        for (int idx = tid; idx < 256; idx += 128)
            hs[j][idx] = d_h1[(g0 + j) * 256 + idx];
    __syncthreads();
    int c = tid;
    float acc[8];
    float bv = b[c];
    #pragma unroll
    for (int j = 0; j < 8; j++) acc[j] = bv;
    for (int k = 0; k < 256; k++) {
        float w = W[k * 128 + c];
        #pragma unroll
        for (int j = 0; j < 8; j++) acc[j] += hs[j][k] * w;
    }
    #pragma unroll
    for (int j = 0; j < 8; j++) d_h2[(g0 + j) * 128 + c] = fmaxf(acc[j], 0.f);
}
__global__ void k_head3(const float* __restrict__ W, const float* __restrict__ b,
                        float* __restrict__ out) {
    int w = threadIdx.x >> 5, lane = threadIdx.x & 31;
    int g = blockIdx.x * 8 + w;
    float s = 0.f;
    for (int k = lane; k < 128; k += 32)
        s += d_h2[g * 128 + k] * __ldg(&W[k]);
    #pragma unroll
    for (int off = 16; off; off >>= 1) s += __shfl_xor_sync(0xffffffffu, s, off);
    if (lane == 0) out[g] = s + __ldg(&b[0]);
}

// ---------------- launch ----------------
extern "C" void kernel_launch(void* const* d_in, const int* in_sizes, int n_in,
                              void* d_out, int out_size) {
    const float* x      = (const float*)d_in[0];
    const int*   ei     = (const int*)d_in[1];
    const float* ea     = (const float*)d_in[2];
    const int*   batch  = (const int*)d_in[3];
    const float* enc_W  = (const float*)d_in[4];
    const float* enc_b  = (const float*)d_in[5];
    const float* edge_W = (const float*)d_in[6];
    const float* edge_b = (const float*)d_in[7];
    const float* mlp_W1 = (const float*)d_in[8];
    const float* mlp_b1 = (const float*)d_in[9];
    const float* mlp_W2 = (const float*)d_in[10];
    const float* mlp_b2 = (const float*)d_in[11];
    const float* bn_g   = (const float*)d_in[12];
    const float* bn_b   = (const float*)d_in[13];
    const float* hW1    = (const float*)d_in[14];
    const float* hb1    = (const float*)d_in[15];
    const float* hW2    = (const float*)d_in[16];
    const float* hb2    = (const float*)d_in[17];
    const float* hW3    = (const float*)d_in[18];
    const float* hb3    = (const float*)d_in[19];
    float* out = (float*)d_out;

    static __nv_bfloat16 *p_zhi = nullptr, *p_zlo = nullptr, *p_thi = nullptr,
                         *p_tlo = nullptr, *p_Wc = nullptr;
    static float* p_z = nullptr;
    if (!p_zhi) {
        cudaGetSymbolAddress((void**)&p_zhi, d_zhi);
        cudaGetSymbolAddress((void**)&p_zlo, d_zlo);
        cudaGetSymbolAddress((void**)&p_thi, d_thi);
        cudaGetSymbolAddress((void**)&p_tlo, d_tlo);
        cudaGetSymbolAddress((void**)&p_Wc, d_Wc);
        cudaGetSymbolAddress((void**)&p_z, d_z);
        cudaFuncSetAttribute(k_mma_gemm<0>, cudaFuncAttributeMaxDynamicSharedMemorySize, SM_TOT);
        cudaFuncSetAttribute(k_mma_gemm<1>, cudaFuncAttributeMaxDynamicSharedMemorySize, SM_TOT);
    }

    // weight conversion (deterministic, every call)
    k_convW<<<(NLAYER * 2 * HID * HID + 255) / 256, 256>>>(mlp_W1, mlp_W2);

    // CSR build (deterministic)
    k_zero_cnt<<<(NN + 255) / 256, 256>>>();
    k_count<<<(NE + 255) / 256, 256>>>(ei);
    k_bsum<<<NSB, 256>>>();
    k_bscan<<<1, 256>>>();
    k_badd<<<NSB, 256>>>();
    k_scatter<<<(NE + 255) / 256, 256>>>(ei);
    k_sortrows<<<(NN + 255) / 256, 256>>>();

    // encoder
    k_encoder<<<(NN + ENC_NPB - 1) / ENC_NPB, 256>>>(x, enc_W, enc_b);

    for (int l = 0; l < NLAYER; l++) {
        k_aggregate<<<(NN + 7) / 8, 256>>>(ei, ea, edge_W + l * EDGE_DIM * HID,
                                           edge_b + l * HID);
        const __nv_bfloat16* W1c = p_Wc + (size_t)(l * 2 + 0) * 2 * 65536;
        const __nv_bfloat16* W2c = p_Wc + (size_t)(l * 2 + 1) * 2 * 65536;
        k_mma_gemm<0><<<NMB, 256, SM_TOT>>>(p_zhi, p_zlo, W1c, mlp_b1 + l * HID,
                                            p_thi, p_tlo, nullptr);
        k_mma_gemm<1><<<NMB, 256, SM_TOT>>>(p_thi, p_tlo, W2c, mlp_b2 + l * HID,
                                            nullptr, nullptr, p_z);
        k_bn_final<<<1, 256>>>(bn_g + l * HID, bn_b + l * HID);
        if (l < NLAYER - 1)
            k_bn_apply<<<(NN * 64 + 255) / 256, 256>>>();
    }

    // pooling (fused with last BN apply) + head
    k_gbounds<<<(NG + 256) / 256, 256>>>(batch);
    k_pool_bn<<<NG, 256>>>();
    k_head1<<<NG / 8, 256>>>(hW1, hb1);
    k_head2<<<NG / 8, 128>>>(hW2, hb2);
    k_head3<<<NG / 8, 256>>>(hW3, hb3, out);
}

// round 7
// speedup vs baseline: 1.0295x; 1.0295x over previous
#include <cuda_runtime.h>
#include <cuda_bf16.h>
#include <math.h>
#include <stdint.h>

#define NN 50000
#define NE 300000
#define HID 256
#define NLAYER 4
#define NG 1024
#define NODE_DIM 11
#define EDGE_DIM 5
#define NSB ((NN + 255) / 256)    // 196 scan blocks
#define NMB ((NN + 127) / 128)    // 391 GEMM M-blocks

// ---------------- persistent scratch (device globals; no allocation) ----------------
__device__ __align__(16) float d_h[NN * HID];
__device__ __align__(16) float d_z[NN * HID];            // GEMM2 out (fp32, for BN)
__device__ __align__(16) __nv_bfloat16 d_zhi[NN * HID];  // GEMM1 input hi
__device__ __align__(16) __nv_bfloat16 d_zlo[NN * HID];
__device__ __align__(16) __nv_bfloat16 d_thi[NN * HID];  // GEMM2 input hi
__device__ __align__(16) __nv_bfloat16 d_tlo[NN * HID];
__device__ __align__(16) __nv_bfloat16 d_Wc[NLAYER * 2 * 2 * HID * HID]; // [l][mat][hl][n][k]
__device__ int   d_cnt[NN];
__device__ int   d_rowptr[NN + 1];
__device__ int   d_eids[NE];
__device__ int   d_bsums[NSB];
__device__ int   d_boff[NSB];
__device__ float d_psum[NMB * HID];
__device__ float d_psq[NMB * HID];
__device__ float d_scale[HID];
__device__ float d_shift[HID];
__device__ int   d_gstart[NG + 1];
__device__ float d_gfeat[NG * 3 * HID];
__device__ float d_h1[NG * HID];
__device__ float d_h2[NG * (HID / 2)];

// ================= portable PTX helpers (sm_80+ baseline; NO tcgen05) =================
__device__ __forceinline__ uint32_t smem_u32(const void* p) {
    uint32_t a;
    asm("{ .reg .u64 t; cvta.to.shared.u64 t, %1; cvt.u32.u64 %0, t; }" : "=r"(a) : "l"(p));
    return a;
}
#define SW128(x) ((x) ^ (((x) >> 3) & 0x70))

__device__ __forceinline__ void cp16(uint32_t dst, const void* src, int srcbytes) {
    asm volatile("cp.async.cg.shared.global [%0], [%1], 16, %2;"
                 :: "r"(dst), "l"(src), "r"(srcbytes) : "memory");
}
#define CP_COMMIT() asm volatile("cp.async.commit_group;" ::: "memory")
#define CP_WAIT0()  asm volatile("cp.async.wait_group 0;" ::: "memory")
#define CP_WAIT1()  asm volatile("cp.async.wait_group 1;" ::: "memory")

__device__ __forceinline__ void ldsm4(uint32_t* r, uint32_t addr) {
    asm volatile("ldmatrix.sync.aligned.m8n8.x4.shared.b16 {%0,%1,%2,%3}, [%4];"
                 : "=r"(r[0]), "=r"(r[1]), "=r"(r[2]), "=r"(r[3]) : "r"(addr));
}
__device__ __forceinline__ void mma16816(float* c, const uint32_t* a, const uint32_t* b) {
    asm volatile("mma.sync.aligned.m16n8k16.row.col.f32.bf16.bf16.f32 "
                 "{%0,%1,%2,%3}, {%4,%5,%6,%7}, {%8,%9}, {%0,%1,%2,%3};"
                 : "+f"(c[0]), "+f"(c[1]), "+f"(c[2]), "+f"(c[3])
                 : "r"(a[0]), "r"(a[1]), "r"(a[2]), "r"(a[3]), "r"(b[0]), "r"(b[1]));
}

// ---------------- CSR build ----------------
__global__ void k_count(const int* __restrict__ ei) {
    int e = blockIdx.x * blockDim.x + threadIdx.x;
    if (e < NE) atomicAdd(&d_cnt[ei[NE + e]], 1);
}
__global__ void k_bsum() {
    __shared__ int red[256];
    int tid = threadIdx.x;
    int i = blockIdx.x * 256 + tid;
    red[tid] = (i < NN) ? d_cnt[i] : 0;
    __syncthreads();
    for (int off = 128; off; off >>= 1) {
        if (tid < off) red[tid] += red[tid + off];
        __syncthreads();
    }
    if (tid == 0) d_bsums[blockIdx.x] = red[0];
}
__global__ void k_bscan() {
    __shared__ int buf[256];
    int tid = threadIdx.x;
    int v = (tid < NSB) ? d_bsums[tid] : 0;
    buf[tid] = v;
    __syncthreads();
    for (int off = 1; off < 256; off <<= 1) {
        int t = (tid >= off) ? buf[tid - off] : 0;
        __syncthreads();
        buf[tid] += t;
        __syncthreads();
    }
    if (tid < NSB) d_boff[tid] = buf[tid] - v;   // exclusive
    if (tid == 0) d_rowptr[NN] = NE;
}
__global__ void k_badd() {
    __shared__ int buf[256];
    int tid = threadIdx.x;
    int i = blockIdx.x * 256 + tid;
    int v = (i < NN) ? d_cnt[i] : 0;
    buf[tid] = v;
    __syncthreads();
    for (int off = 1; off < 256; off <<= 1) {
        int t = (tid >= off) ? buf[tid - off] : 0;
        __syncthreads();
        buf[tid] += t;
        __syncthreads();
    }
    if (i < NN) {
        int excl = buf[tid] - v + d_boff[blockIdx.x];
        d_rowptr[i] = excl;
        d_cnt[i] = excl;   // scatter cursor
    }
}
__global__ void k_scatter(const int* __restrict__ ei) {
    int e = blockIdx.x * blockDim.x + threadIdx.x;
    if (e < NE) {
        int pos = atomicAdd(&d_cnt[ei[NE + e]], 1);
        d_eids[pos] = e;
    }
}
__global__ void k_sortrows() {
    int i = blockIdx.x * blockDim.x + threadIdx.x;
    if (i >= NN) return;
    int rs = d_rowptr[i], re = d_rowptr[i + 1];
    for (int a = rs + 1; a < re; a++) {
        int key = d_eids[a];
        int b = a - 1;
        while (b >= rs && d_eids[b] > key) { d_eids[b + 1] = d_eids[b]; b--; }
        d_eids[b + 1] = key;
    }
}

// ---------------- encoder ----------------
#define ENC_NPB 64
__global__ void k_encoder(const float* __restrict__ x, const float* __restrict__ W,
                          const float* __restrict__ b) {
    __shared__ float Ws[NODE_DIM][HID];
    __shared__ float bs[HID];
    int c = threadIdx.x;
    #pragma unroll
    for (int k = 0; k < NODE_DIM; k++) Ws[k][c] = W[k * HID + c];
    bs[c] = b[c];
    __syncthreads();
    int n0 = blockIdx.x * ENC_NPB;
    for (int i = 0; i < ENC_NPB; i++) {
        int n = n0 + i;
        if (n >= NN) break;
        float acc = bs[c];
        #pragma unroll
        for (int k = 0; k < NODE_DIM; k++) acc += __ldg(&x[n * NODE_DIM + k]) * Ws[k][c];
        d_h[n * HID + c] = fmaxf(acc, 0.f);
    }
}

// ---------------- weight conversion: W -> transposed bf16 hi/lo ----------------
__global__ void k_convW(const float* __restrict__ W1, const float* __restrict__ W2) {
    int idx = blockIdx.x * blockDim.x + threadIdx.x;
    if (idx >= NLAYER * 2 * HID * HID) return;
    int e = idx & 65535;
    int lm = idx >> 16;                // l*2 + mat
    int l = lm >> 1, mat = lm & 1;
    int n = e & 255, k = e >> 8;
    const float* W = mat ? W2 : W1;
    float w = W[l * 65536 + k * 256 + n];
    __nv_bfloat16 hi = __float2bfloat16(w);
    __nv_bfloat16 lo = __float2bfloat16(w - __bfloat162float(hi));
    d_Wc[(size_t)(lm * 2 + 0) * 65536 + n * 256 + k] = hi;
    d_Wc[(size_t)(lm * 2 + 1) * 65536 + n * 256 + k] = lo;
}

// ---------------- GINE aggregation ----------------
__global__ void k_aggregate(const int* __restrict__ ei, const float* __restrict__ ea,
                            const float* __restrict__ eW, const float* __restrict__ eb) {
    __shared__ float Ws[EDGE_DIM][HID];
    __shared__ float bs[HID];
    int c = threadIdx.x;
    #pragma unroll
    for (int k = 0; k < EDGE_DIM; k++) Ws[k][c] = eW[k * HID + c];
    bs[c] = eb[c];
    __syncthreads();
    int n0 = blockIdx.x * 8;
    for (int i = 0; i < 8; i++) {
        int n = n0 + i;
        if (n >= NN) break;
        int rs = d_rowptr[n], re = d_rowptr[n + 1];
        float acc = d_h[n * HID + c];
        for (int p = rs; p < re; p++) {
            int e = d_eids[p];
            int src = ei[e];
            float ec = bs[c];
            #pragma unroll
            for (int k = 0; k < EDGE_DIM; k++) ec += __ldg(&ea[e * EDGE_DIM + k]) * Ws[k][c];
            acc += fmaxf(d_h[src * HID + c] + ec, 0.f);
        }
        __nv_bfloat16 hi = __float2bfloat16(acc);
        d_zhi[n * HID + c] = hi;
        d_zlo[n * HID + c] = __float2bfloat16(acc - __bfloat162float(hi));
    }
}

// ---------------- HMMA GEMM (R4 best config): 128x128 CTA, 2 CTAs/SM ----------------
// Virtual K = 768: term 0 = Ah*Wh, term 1 = Ah*Wl, term 2 = Al*Wh.
// 8 warps = 2(M) x 4(N); warp tile 64x32; k-chunk 64, double-buffered cp.async.
// MODE 0: out = relu(D+bias) split -> (Ohi, Olo). MODE 1: out = D+bias -> Of (fp32) + BN partial stats.
#define SM_BUF 32768   // 16KB A + 16KB B per buffer

__device__ __forceinline__ void g_load_chunk(
    uint32_t sb, int buf, int vk, int tid, int bm, int bn,
    const __nv_bfloat16* __restrict__ Ahi, const __nv_bfloat16* __restrict__ Alo,
    const __nv_bfloat16* __restrict__ Wc) {
    int term = vk >> 8, kk = vk & 255;
    const __nv_bfloat16* Asrc = (term == 2) ? Alo : Ahi;
    const __nv_bfloat16* Bsrc = Wc + ((term == 1) ? 65536 : 0);
    uint32_t abase = sb + buf * SM_BUF;
    uint32_t bbase = abase + 16384;
    #pragma unroll
    for (int t = 0; t < 4; t++) {
        int idx = tid + t * 256;
        int row = idx >> 3, seg = idx & 7;
        int gm = bm + row;
        cp16(abase + SW128(row * 128 + seg * 16),
             Asrc + (size_t)gm * 256 + kk + seg * 8, (gm < NN) ? 16 : 0);
    }
    #pragma unroll
    for (int t = 0; t < 4; t++) {
        int idx = tid + t * 256;
        int row = idx >> 3, seg = idx & 7;
        cp16(bbase + SW128(row * 128 + seg * 16),
             Bsrc + (size_t)(bn + row) * 256 + kk + seg * 8, 16);
    }
    CP_COMMIT();
}

template <int MODE>
__global__ __launch_bounds__(256, 2)
void k_mma_gemm(const __nv_bfloat16* __restrict__ Ahi, const __nv_bfloat16* __restrict__ Alo,
                const __nv_bfloat16* __restrict__ Wc,   // [2 hl][256 n][256 k] bf16
                const float* __restrict__ bias,
                __nv_bfloat16* __restrict__ Ohi, __nv_bfloat16* __restrict__ Olo,
                float* __restrict__ Of) {
    extern __shared__ char smem[];
    uint32_t sb = smem_u32(smem);
    int tid = threadIdx.x, wid = tid >> 5, lane = tid & 31;
    int bm = blockIdx.y * 128;
    int bn = blockIdx.x * 128;
    int wm = wid & 1, wn = wid >> 1;

    float c[4][4][4];
    #pragma unroll
    for (int mt = 0; mt < 4; mt++)
        #pragma unroll
        for (int nt = 0; nt < 4; nt++)
            #pragma unroll
            for (int q = 0; q < 4; q++) c[mt][nt][q] = 0.f;

    g_load_chunk(sb, 0, 0, tid, bm, bn, Ahi, Alo, Wc);

    #pragma unroll 1
    for (int i = 0; i < 12; i++) {
        if (i + 1 < 12) {
            g_load_chunk(sb, (i + 1) & 1, (i + 1) * 64, tid, bm, bn, Ahi, Alo, Wc);
            CP_WAIT1();
        } else {
            CP_WAIT0();
        }
        __syncthreads();
        uint32_t abase = sb + (i & 1) * SM_BUF;
        uint32_t bbase = abase + 16384;
        #pragma unroll
        for (int ks = 0; ks < 4; ks++) {
            uint32_t a[4][4], b[4][2];
            #pragma unroll
            for (int mt = 0; mt < 4; mt++) {
                int row = wm * 64 + mt * 16 + (lane & 15);
                ldsm4(a[mt], abase + SW128(row * 128 + ks * 32 + (lane >> 4) * 16));
            }
            #pragma unroll
            for (int p = 0; p < 2; p++) {   // each ldsm4: two 8-col n-tiles x two k-halves
                uint32_t r4[4];
                int row = wn * 32 + (p * 2 + (lane >> 4)) * 8 + (lane & 7);
                ldsm4(r4, bbase + SW128(row * 128 + ks * 32 + ((lane >> 3) & 1) * 16));
                b[2 * p + 0][0] = r4[0]; b[2 * p + 0][1] = r4[1];
                b[2 * p + 1][0] = r4[2]; b[2 * p + 1][1] = r4[3];
            }
            #pragma unroll
            for (int mt = 0; mt < 4; mt++)
                #pragma unroll
                for (int nt = 0; nt < 4; nt++)
                    mma16816(c[mt][nt], a[mt], b[nt]);
        }
        __syncthreads();
    }

    // epilogue
    int gid = lane >> 2, tig = lane & 3;
    float s[8], s2[8];
    if (MODE == 1) {
        #pragma unroll
        for (int j = 0; j < 8; j++) { s[j] = 0.f; s2[j] = 0.f; }
    }
    #pragma unroll
    for (int mt = 0; mt < 4; mt++) {
        #pragma unroll
        for (int nt = 0; nt < 4; nt++) {
            int col = bn + wn * 32 + nt * 8 + tig * 2;
            float b0 = __ldg(&bias[col]), b1 = __ldg(&bias[col + 1]);
            #pragma unroll
            for (int half = 0; half < 2; half++) {
                int r = bm + wm * 64 + mt * 16 + gid + half * 8;
                if (r >= NN) continue;
                float v0 = c[mt][nt][half * 2 + 0] + b0;
                float v1 = c[mt][nt][half * 2 + 1] + b1;
                if (MODE == 0) {
                    v0 = fmaxf(v0, 0.f); v1 = fmaxf(v1, 0.f);
                    __nv_bfloat16 h0 = __float2bfloat16(v0), h1 = __float2bfloat16(v1);
                    __nv_bfloat16 l0 = __float2bfloat16(v0 - __bfloat162float(h0));
                    __nv_bfloat16 l1 = __float2bfloat16(v1 - __bfloat162float(h1));
                    *(__nv_bfloat162*)(Ohi + (size_t)r * 256 + col) = __halves2bfloat162(h0, h1);
                    *(__nv_bfloat162*)(Olo + (size_t)r * 256 + col) = __halves2bfloat162(l0, l1);
                } else {
                    *(float2*)(Of + (size_t)r * 256 + col) = make_float2(v0, v1);
                    s[nt * 2 + 0] += v0; s2[nt * 2 + 0] += v0 * v0;
                    s[nt * 2 + 1] += v1; s2[nt * 2 + 1] += v1 * v1;
                }
            }
        }
    }
    if (MODE == 1) {
        #pragma unroll
        for (int j = 0; j < 8; j++) {
            #pragma unroll
            for (int off = 4; off < 32; off <<= 1) {
                s[j]  += __shfl_xor_sync(0xffffffffu, s[j], off);
                s2[j] += __shfl_xor_sync(0xffffffffu, s2[j], off);
            }
        }
        float* ss  = (float*)smem;          // [2][128]
        float* ssq = ss + 256;              // [2][128]
        if (gid == 0) {
            #pragma unroll
            for (int nt = 0; nt < 4; nt++) {
                #pragma unroll
                for (int q = 0; q < 2; q++) {
                    int cl = wn * 32 + nt * 8 + tig * 2 + q;
                    ss[wm * 128 + cl]  = s[nt * 2 + q];
                    ssq[wm * 128 + cl] = s2[nt * 2 + q];
                }
            }
        }
        __syncthreads();
        if (tid < 128) {
            int slot = blockIdx.y * 256 + bn + tid;
            d_psum[slot] = ss[tid] + ss[128 + tid];
            d_psq[slot]  = ssq[tid] + ssq[128 + tid];
        }
    }
}

// ---------------- BatchNorm finalize + apply ----------------
__global__ void k_bn_final(const float* __restrict__ g, const float* __restrict__ b) {
    int c = threadIdx.x;
    float s = 0.f, s2 = 0.f;
    for (int blk = 0; blk < NMB; blk++) {
        s += d_psum[blk * HID + c];
        s2 += d_psq[blk * HID + c];
    }
    float mu = s / (float)NN;
    float var = s2 / (float)NN - mu * mu;
    float sc = g[c] * rsqrtf(var + 1e-5f);
    d_scale[c] = sc;
    d_shift[c] = b[c] - mu * sc;
}
__global__ void k_bn_apply() {
    int idx = blockIdx.x * blockDim.x + threadIdx.x;   // float4 index
    if (idx >= NN * 64) return;
    int c4 = idx & 63;
    float4 z = *(const float4*)(d_z + idx * 4);
    float4 h = *(const float4*)(d_h + idx * 4);
    float4 sc = *(const float4*)(d_scale + c4 * 4);
    float4 sh = *(const float4*)(d_shift + c4 * 4);
    h.x += fmaxf(z.x * sc.x + sh.x, 0.f);
    h.y += fmaxf(z.y * sc.y + sh.y, 0.f);
    h.z += fmaxf(z.z * sc.z + sh.z, 0.f);
    h.w += fmaxf(z.w * sc.w + sh.w, 0.f);
    *(float4*)(d_h + idx * 4) = h;
}

// ---------------- graph pooling (fused with layer-3 BN apply) ----------------
__global__ void k_gbounds(const int* __restrict__ batch) {
    int g = blockIdx.x * blockDim.x + threadIdx.x;
    if (g > NG) return;
    if (g == NG) { d_gstart[NG] = NN; return; }
    int lo = 0, hi = NN;
    while (lo < hi) {
        int mid = (lo + hi) >> 1;
        if (batch[mid] < g) lo = mid + 1; else hi = mid;
    }
    d_gstart[g] = lo;
}
__global__ void k_pool_bn() {
    int g = blockIdx.x, c = threadIdx.x;
    int s0 = d_gstart[g], s1 = d_gstart[g + 1];
    float sc = d_scale[c], sh = d_shift[c];
    float sum = 0.f;
    float mx = -INFINITY;
    for (int n = s0; n < s1; n++) {
        float hn = fmaxf(d_z[n * HID + c] * sc + sh, 0.f) + d_h[n * HID + c];
        sum += hn;
        mx = fmaxf(mx, hn);
    }
    float cntf = (float)(s1 - s0);
    float mean = sum / fmaxf(cntf, 1.f);
    d_gfeat[g * 768 + c] = mean;
    d_gfeat[g * 768 + 256 + c] = sum;
    d_gfeat[g * 768 + 512 + c] = mx;
}

// ---------------- head ----------------
__global__ void k_head1(const float* __restrict__ W, const float* __restrict__ b) {
    __shared__ float gs[8][768];
    int tid = threadIdx.x;
    int g0 = blockIdx.x * 8;
    for (int j = 0; j < 8; j++)
        for (int idx = tid; idx < 768; idx += 256)
            gs[j][idx] = d_gfeat[(g0 + j) * 768 + idx];
    __syncthreads();
    int c = tid;
    float acc[8];
    float bv = b[c];
    #pragma unroll
    for (int j = 0; j < 8; j++) acc[j] = bv;
    for (int k = 0; k < 768; k++) {
        float w = W[k * 256 + c];
        #pragma unroll
        for (int j = 0; j < 8; j++) acc[j] += gs[j][k] * w;
    }
    #pragma unroll
    for (int j = 0; j < 8; j++) d_h1[(g0 + j) * 256 + c] = fmaxf(acc[j], 0.f);
}
__global__ void k_head2(const float* __restrict__ W, const float* __restrict__ b) {
    __shared__ float hs[8][256];
    int tid = threadIdx.x;  // 128 threads
    int g0 = blockIdx.x * 8;
    for (int j = 0; j < 8; j++)
        for (int idx = tid; idx < 256; idx += 128)
            hs[j][idx] = d_h1[(g0 + j) * 256 + idx];
    __syncthreads();
    int c = tid;
    float acc[8];
    float bv = b[c];
    #pragma unroll
    for (int j = 0; j < 8; j++) acc[j] = bv;
    for (int k = 0; k < 256; k++) {
        float w = W[k * 128 + c];
        #pragma unroll
        for (int j = 0; j < 8; j++) acc[j] += hs[j][k] * w;
    }
    #pragma unroll
    for (int j = 0; j < 8; j++) d_h2[(g0 + j) * 128 + c] = fmaxf(acc[j], 0.f);
}
__global__ void k_head3(const float* __restrict__ W, const float* __restrict__ b,
                        float* __restrict__ out) {
    int w = threadIdx.x >> 5, lane = threadIdx.x & 31;
    int g = blockIdx.x * 8 + w;
    float s = 0.f;
    for (int k = lane; k < 128; k += 32)
        s += d_h2[g * 128 + k] * __ldg(&W[k]);
    #pragma unroll
    for (int off = 16; off; off >>= 1) s += __shfl_xor_sync(0xffffffffu, s, off);
    if (lane == 0) out[g] = s + __ldg(&b[0]);
}

// ---------------- launch ----------------
extern "C" void kernel_launch(void* const* d_in, const int* in_sizes, int n_in,
                              void* d_out, int out_size) {
    const float* x      = (const float*)d_in[0];
    const int*   ei     = (const int*)d_in[1];
    const float* ea     = (const float*)d_in[2];
    const int*   batch  = (const int*)d_in[3];
    const float* enc_W  = (const float*)d_in[4];
    const float* enc_b  = (const float*)d_in[5];
    const float* edge_W = (const float*)d_in[6];
    const float* edge_b = (const float*)d_in[7];
    const float* mlp_W1 = (const float*)d_in[8];
    const float* mlp_b1 = (const float*)d_in[9];
    const float* mlp_W2 = (const float*)d_in[10];
    const float* mlp_b2 = (const float*)d_in[11];
    const float* bn_g   = (const float*)d_in[12];
    const float* bn_b   = (const float*)d_in[13];
    const float* hW1    = (const float*)d_in[14];
    const float* hb1    = (const float*)d_in[15];
    const float* hW2    = (const float*)d_in[16];
    const float* hb2    = (const float*)d_in[17];
    const float* hW3    = (const float*)d_in[18];
    const float* hb3    = (const float*)d_in[19];
    float* out = (float*)d_out;

    static __nv_bfloat16 *p_zhi = nullptr, *p_zlo = nullptr, *p_thi = nullptr,
                         *p_tlo = nullptr, *p_Wc = nullptr;
    static float* p_z = nullptr;
    static int* p_cnt = nullptr;
    if (!p_zhi) {
        cudaGetSymbolAddress((void**)&p_zhi, d_zhi);
        cudaGetSymbolAddress((void**)&p_zlo, d_zlo);
        cudaGetSymbolAddress((void**)&p_thi, d_thi);
        cudaGetSymbolAddress((void**)&p_tlo, d_tlo);
        cudaGetSymbolAddress((void**)&p_Wc, d_Wc);
        cudaGetSymbolAddress((void**)&p_z, d_z);
        cudaGetSymbolAddress((void**)&p_cnt, d_cnt);
        cudaFuncSetAttribute(k_mma_gemm<0>, cudaFuncAttributeMaxDynamicSharedMemorySize, 2 * SM_BUF);
        cudaFuncSetAttribute(k_mma_gemm<1>, cudaFuncAttributeMaxDynamicSharedMemorySize, 2 * SM_BUF);
    }

    // weight conversion (deterministic, every call)
    k_convW<<<(NLAYER * 2 * HID * HID + 255) / 256, 256>>>(mlp_W1, mlp_W2);

    // CSR build (deterministic)
    cudaMemsetAsync(p_cnt, 0, NN * sizeof(int));
    k_count<<<(NE + 255) / 256, 256>>>(ei);
    k_bsum<<<NSB, 256>>>();
    k_bscan<<<1, 256>>>();
    k_badd<<<NSB, 256>>>();
    k_scatter<<<(NE + 255) / 256, 256>>>(ei);
    k_sortrows<<<(NN + 255) / 256, 256>>>();

    // encoder
    k_encoder<<<(NN + ENC_NPB - 1) / ENC_NPB, 256>>>(x, enc_W, enc_b);

    dim3 gemm_grid(2, NMB);   // (N/128, M/128)
    for (int l = 0; l < NLAYER; l++) {
        k_aggregate<<<(NN + 7) / 8, 256>>>(ei, ea, edge_W + l * EDGE_DIM * HID,
                                           edge_b + l * HID);
        const __nv_bfloat16* W1c = p_Wc + (size_t)(l * 2 + 0) * 2 * 65536;
        const __nv_bfloat16* W2c = p_Wc + (size_t)(l * 2 + 1) * 2 * 65536;
        k_mma_gemm<0><<<gemm_grid, 256, 2 * SM_BUF>>>(p_zhi, p_zlo, W1c, mlp_b1 + l * HID,
                                                      p_thi, p_tlo, nullptr);
        k_mma_gemm<1><<<gemm_grid, 256, 2 * SM_BUF>>>(p_thi, p_tlo, W2c, mlp_b2 + l * HID,
                                                      nullptr, nullptr, p_z);
        k_bn_final<<<1, 256>>>(bn_g + l * HID, bn_b + l * HID);
        if (l < NLAYER - 1)
            k_bn_apply<<<(NN * 64 + 255) / 256, 256>>>();
    }

    // pooling (fused with last BN apply) + head
    k_gbounds<<<(NG + 256) / 256, 256>>>(batch);
    k_pool_bn<<<NG, 256>>>();
    k_head1<<<NG / 8, 256>>>(hW1, hb1);
    k_head2<<<NG / 8, 128>>>(hW2, hb2);
    k_head3<<<NG / 8, 256>>>(hW3, hb3, out);
}

// round 8
// speedup vs baseline: 1.0702x; 1.0395x over previous
#include <cuda_runtime.h>
#include <cuda_bf16.h>
#include <math.h>
#include <stdint.h>

#define NN 50000
#define NE 300000
#define HID 256
#define NLAYER 4
#define NG 1024
#define NODE_DIM 11
#define EDGE_DIM 5
#define NSB ((NN + 255) / 256)    // 196 scan blocks
#define NMB ((NN + 127) / 128)    // 391 GEMM M-blocks

// ---------------- persistent scratch (device globals; no allocation) ----------------
__device__ __align__(16) float d_h[NN * HID];
__device__ __align__(16) float d_z[NN * HID];            // GEMM2 out (fp32, for BN)
__device__ __align__(16) __nv_bfloat16 d_zhi[NN * HID];  // GEMM1 input hi
__device__ __align__(16) __nv_bfloat16 d_zlo[NN * HID];
__device__ __align__(16) __nv_bfloat16 d_thi[NN * HID];  // GEMM2 input hi
__device__ __align__(16) __nv_bfloat16 d_tlo[NN * HID];
__device__ __align__(16) __nv_bfloat16 d_Wc[NLAYER * 2 * 2 * HID * HID]; // [l][mat][hl][n][k]
__device__ int   d_cnt[NN];
__device__ int   d_rowptr[NN + 1];
__device__ int   d_eids[NE];
__device__ int   d_bsums[NSB];
__device__ int   d_boff[NSB];
__device__ float d_psum[NMB * HID];
__device__ float d_psq[NMB * HID];
__device__ float d_scale[HID];
__device__ float d_shift[HID];
__device__ int   d_bn_ctr;
__device__ int   d_gstart[NG + 1];
__device__ float d_gfeat[NG * 3 * HID];

// ================= portable PTX helpers (sm_80+ baseline; NO tcgen05) =================
__device__ __forceinline__ uint32_t smem_u32(const void* p) {
    uint32_t a;
    asm("{ .reg .u64 t; cvta.to.shared.u64 t, %1; cvt.u32.u64 %0, t; }" : "=r"(a) : "l"(p));
    return a;
}
#define SW128(x) ((x) ^ (((x) >> 3) & 0x70))

__device__ __forceinline__ void cp16(uint32_t dst, const void* src, int srcbytes) {
    asm volatile("cp.async.cg.shared.global [%0], [%1], 16, %2;"
                 :: "r"(dst), "l"(src), "r"(srcbytes) : "memory");
}
#define CP_COMMIT() asm volatile("cp.async.commit_group;" ::: "memory")
#define CP_WAIT0()  asm volatile("cp.async.wait_group 0;" ::: "memory")
#define CP_WAIT1()  asm volatile("cp.async.wait_group 1;" ::: "memory")

__device__ __forceinline__ void ldsm4(uint32_t* r, uint32_t addr) {
    asm volatile("ldmatrix.sync.aligned.m8n8.x4.shared.b16 {%0,%1,%2,%3}, [%4];"
                 : "=r"(r[0]), "=r"(r[1]), "=r"(r[2]), "=r"(r[3]) : "r"(addr));
}
__device__ __forceinline__ void mma16816(float* c, const uint32_t* a, const uint32_t* b) {
    asm volatile("mma.sync.aligned.m16n8k16.row.col.f32.bf16.bf16.f32 "
                 "{%0,%1,%2,%3}, {%4,%5,%6,%7}, {%8,%9}, {%0,%1,%2,%3};"
                 : "+f"(c[0]), "+f"(c[1]), "+f"(c[2]), "+f"(c[3])
                 : "r"(a[0]), "r"(a[1]), "r"(a[2]), "r"(a[3]), "r"(b[0]), "r"(b[1]));
}

// ---------------- CSR build ----------------
__global__ void k_count(const int* __restrict__ ei) {
    int e = blockIdx.x * blockDim.x + threadIdx.x;
    if (e < NE) atomicAdd(&d_cnt[ei[NE + e]], 1);
}
__global__ void k_bsum() {
    __shared__ int red[256];
    int tid = threadIdx.x;
    int i = blockIdx.x * 256 + tid;
    red[tid] = (i < NN) ? d_cnt[i] : 0;
    __syncthreads();
    for (int off = 128; off; off >>= 1) {
        if (tid < off) red[tid] += red[tid + off];
        __syncthreads();
    }
    if (tid == 0) d_bsums[blockIdx.x] = red[0];
}
__global__ void k_bscan() {
    __shared__ int buf[256];
    int tid = threadIdx.x;
    int v = (tid < NSB) ? d_bsums[tid] : 0;
    buf[tid] = v;
    __syncthreads();
    for (int off = 1; off < 256; off <<= 1) {
        int t = (tid >= off) ? buf[tid - off] : 0;
        __syncthreads();
        buf[tid] += t;
        __syncthreads();
    }
    if (tid < NSB) d_boff[tid] = buf[tid] - v;   // exclusive
    if (tid == 0) d_rowptr[NN] = NE;
}
__global__ void k_badd() {
    __shared__ int buf[256];
    int tid = threadIdx.x;
    int i = blockIdx.x * 256 + tid;
    int v = (i < NN) ? d_cnt[i] : 0;
    buf[tid] = v;
    __syncthreads();
    for (int off = 1; off < 256; off <<= 1) {
        int t = (tid >= off) ? buf[tid - off] : 0;
        __syncthreads();
        buf[tid] += t;
        __syncthreads();
    }
    if (i < NN) {
        int excl = buf[tid] - v + d_boff[blockIdx.x];
        d_rowptr[i] = excl;
        d_cnt[i] = excl;   // scatter cursor
    }
}
__global__ void k_scatter(const int* __restrict__ ei) {
    int e = blockIdx.x * blockDim.x + threadIdx.x;
    if (e < NE) {
        int pos = atomicAdd(&d_cnt[ei[NE + e]], 1);
        d_eids[pos] = e;
    }
}
__global__ void k_sortrows() {
    int i = blockIdx.x * blockDim.x + threadIdx.x;
    if (i >= NN) return;
    int rs = d_rowptr[i], re = d_rowptr[i + 1];
    for (int a = rs + 1; a < re; a++) {
        int key = d_eids[a];
        int b = a - 1;
        while (b >= rs && d_eids[b] > key) { d_eids[b + 1] = d_eids[b]; b--; }
        d_eids[b + 1] = key;
    }
}

// ---------------- encoder ----------------
#define ENC_NPB 64
__global__ void k_encoder(const float* __restrict__ x, const float* __restrict__ W,
                          const float* __restrict__ b) {
    __shared__ float Ws[NODE_DIM][HID];
    __shared__ float bs[HID];
    int c = threadIdx.x;
    #pragma unroll
    for (int k = 0; k < NODE_DIM; k++) Ws[k][c] = W[k * HID + c];
    bs[c] = b[c];
    __syncthreads();
    int n0 = blockIdx.x * ENC_NPB;
    for (int i = 0; i < ENC_NPB; i++) {
        int n = n0 + i;
        if (n >= NN) break;
        float acc = bs[c];
        #pragma unroll
        for (int k = 0; k < NODE_DIM; k++) acc += __ldg(&x[n * NODE_DIM + k]) * Ws[k][c];
        d_h[n * HID + c] = fmaxf(acc, 0.f);
    }
}

// ---------------- weight conversion: W -> transposed bf16 hi/lo ----------------
__global__ void k_convW(const float* __restrict__ W1, const float* __restrict__ W2) {
    int idx = blockIdx.x * blockDim.x + threadIdx.x;
    if (idx >= NLAYER * 2 * HID * HID) return;
    int e = idx & 65535;
    int lm = idx >> 16;                // l*2 + mat
    int l = lm >> 1, mat = lm & 1;
    int n = e & 255, k = e >> 8;
    const float* W = mat ? W2 : W1;
    float w = W[l * 65536 + k * 256 + n];
    __nv_bfloat16 hi = __float2bfloat16(w);
    __nv_bfloat16 lo = __float2bfloat16(w - __bfloat162float(hi));
    d_Wc[(size_t)(lm * 2 + 0) * 65536 + n * 256 + k] = hi;
    d_Wc[(size_t)(lm * 2 + 1) * 65536 + n * 256 + k] = lo;
}

// ---------------- GINE aggregation: warp-per-node, register-cached edge weights ----------------
__global__ __launch_bounds__(256)
void k_aggregate(const int* __restrict__ ei, const float* __restrict__ ea,
                 const float* __restrict__ eW, const float* __restrict__ eb) {
    int wid = threadIdx.x >> 5, lane = threadIdx.x & 31;
    int n = blockIdx.x * 8 + wid;
    int c0 = lane * 8;

    float Wr[EDGE_DIM][8], br[8];
    #pragma unroll
    for (int k = 0; k < EDGE_DIM; k++)
        #pragma unroll
        for (int j = 0; j < 8; j++) Wr[k][j] = __ldg(&eW[k * HID + c0 + j]);
    #pragma unroll
    for (int j = 0; j < 8; j++) br[j] = __ldg(&eb[c0 + j]);

    if (n >= NN) return;
    int rs = d_rowptr[n], re = d_rowptr[n + 1];

    float acc[8];
    {
        const float4* hr = (const float4*)(d_h + (size_t)n * HID + c0);
        float4 a0 = hr[0], a1 = hr[1];
        acc[0] = a0.x; acc[1] = a0.y; acc[2] = a0.z; acc[3] = a0.w;
        acc[4] = a1.x; acc[5] = a1.y; acc[6] = a1.z; acc[7] = a1.w;
    }
    for (int p = rs; p < re; p++) {
        int e = d_eids[p];
        int src = __ldg(&ei[e]);
        float e0 = __ldg(&ea[e * 5 + 0]);
        float e1 = __ldg(&ea[e * 5 + 1]);
        float e2 = __ldg(&ea[e * 5 + 2]);
        float e3 = __ldg(&ea[e * 5 + 3]);
        float e4 = __ldg(&ea[e * 5 + 4]);
        const float4* hs = (const float4*)(d_h + (size_t)src * HID + c0);
        float4 h0 = hs[0], h1 = hs[1];
        float hv[8] = { h0.x, h0.y, h0.z, h0.w, h1.x, h1.y, h1.z, h1.w };
        #pragma unroll
        for (int j = 0; j < 8; j++) {
            float ec = br[j];
            ec = fmaf(e0, Wr[0][j], ec);
            ec = fmaf(e1, Wr[1][j], ec);
            ec = fmaf(e2, Wr[2][j], ec);
            ec = fmaf(e3, Wr[3][j], ec);
            ec = fmaf(e4, Wr[4][j], ec);
            acc[j] += fmaxf(hv[j] + ec, 0.f);
        }
    }
    __nv_bfloat162 hv2[4], lv2[4];
    #pragma unroll
    for (int q = 0; q < 4; q++) {
        __nv_bfloat16 h0 = __float2bfloat16(acc[2 * q]);
        __nv_bfloat16 h1 = __float2bfloat16(acc[2 * q + 1]);
        __nv_bfloat16 l0 = __float2bfloat16(acc[2 * q] - __bfloat162float(h0));
        __nv_bfloat16 l1 = __float2bfloat16(acc[2 * q + 1] - __bfloat162float(h1));
        hv2[q] = __halves2bfloat162(h0, h1);
        lv2[q] = __halves2bfloat162(l0, l1);
    }
    *(uint4*)(d_zhi + (size_t)n * HID + c0) = *(const uint4*)hv2;
    *(uint4*)(d_zlo + (size_t)n * HID + c0) = *(const uint4*)lv2;
}

// ---------------- HMMA GEMM (R4 best config): 128x128 CTA, 2 CTAs/SM ----------------
// Virtual K = 768: term 0 = Ah*Wh, term 1 = Ah*Wl, term 2 = Al*Wh.
// MODE 0: out = relu(D+bias) split -> (Ohi, Olo).
// MODE 1: out = D+bias -> Of (fp32) + BN stats; last CTA finalizes scale/shift.
#define SM_BUF 32768   // 16KB A + 16KB B per buffer

__device__ __forceinline__ void g_load_chunk(
    uint32_t sb, int buf, int vk, int tid, int bm, int bn,
    const __nv_bfloat16* __restrict__ Ahi, const __nv_bfloat16* __restrict__ Alo,
    const __nv_bfloat16* __restrict__ Wc) {
    int term = vk >> 8, kk = vk & 255;
    const __nv_bfloat16* Asrc = (term == 2) ? Alo : Ahi;
    const __nv_bfloat16* Bsrc = Wc + ((term == 1) ? 65536 : 0);
    uint32_t abase = sb + buf * SM_BUF;
    uint32_t bbase = abase + 16384;
    #pragma unroll
    for (int t = 0; t < 4; t++) {
        int idx = tid + t * 256;
        int row = idx >> 3, seg = idx & 7;
        int gm = bm + row;
        cp16(abase + SW128(row * 128 + seg * 16),
             Asrc + (size_t)gm * 256 + kk + seg * 8, (gm < NN) ? 16 : 0);
    }
    #pragma unroll
    for (int t = 0; t < 4; t++) {
        int idx = tid + t * 256;
        int row = idx >> 3, seg = idx & 7;
        cp16(bbase + SW128(row * 128 + seg * 16),
             Bsrc + (size_t)(bn + row) * 256 + kk + seg * 8, 16);
    }
    CP_COMMIT();
}

template <int MODE>
__global__ __launch_bounds__(256, 2)
void k_mma_gemm(const __nv_bfloat16* __restrict__ Ahi, const __nv_bfloat16* __restrict__ Alo,
                const __nv_bfloat16* __restrict__ Wc,   // [2 hl][256 n][256 k] bf16
                const float* __restrict__ bias,
                __nv_bfloat16* __restrict__ Ohi, __nv_bfloat16* __restrict__ Olo,
                float* __restrict__ Of,
                const float* __restrict__ bng, const float* __restrict__ bnb) {
    extern __shared__ char smem[];
    uint32_t sb = smem_u32(smem);
    int tid = threadIdx.x, wid = tid >> 5, lane = tid & 31;
    int bm = blockIdx.y * 128;
    int bn = blockIdx.x * 128;
    int wm = wid & 1, wn = wid >> 1;

    float c[4][4][4];
    #pragma unroll
    for (int mt = 0; mt < 4; mt++)
        #pragma unroll
        for (int nt = 0; nt < 4; nt++)
            #pragma unroll
            for (int q = 0; q < 4; q++) c[mt][nt][q] = 0.f;

    g_load_chunk(sb, 0, 0, tid, bm, bn, Ahi, Alo, Wc);

    #pragma unroll 1
    for (int i = 0; i < 12; i++) {
        if (i + 1 < 12) {
            g_load_chunk(sb, (i + 1) & 1, (i + 1) * 64, tid, bm, bn, Ahi, Alo, Wc);
            CP_WAIT1();
        } else {
            CP_WAIT0();
        }
        __syncthreads();
        uint32_t abase = sb + (i & 1) * SM_BUF;
        uint32_t bbase = abase + 16384;
        #pragma unroll
        for (int ks = 0; ks < 4; ks++) {
            uint32_t a[4][4], b[4][2];
            #pragma unroll
            for (int mt = 0; mt < 4; mt++) {
                int row = wm * 64 + mt * 16 + (lane & 15);
                ldsm4(a[mt], abase + SW128(row * 128 + ks * 32 + (lane >> 4) * 16));
            }
            #pragma unroll
            for (int p = 0; p < 2; p++) {
                uint32_t r4[4];
                int row = wn * 32 + (p * 2 + (lane >> 4)) * 8 + (lane & 7);
                ldsm4(r4, bbase + SW128(row * 128 + ks * 32 + ((lane >> 3) & 1) * 16));
                b[2 * p + 0][0] = r4[0]; b[2 * p + 0][1] = r4[1];
                b[2 * p + 1][0] = r4[2]; b[2 * p + 1][1] = r4[3];
            }
            #pragma unroll
            for (int mt = 0; mt < 4; mt++)
                #pragma unroll
                for (int nt = 0; nt < 4; nt++)
                    mma16816(c[mt][nt], a[mt], b[nt]);
        }
        __syncthreads();
    }

    // epilogue
    int gid = lane >> 2, tig = lane & 3;
    float s[8], s2[8];
    if (MODE == 1) {
        #pragma unroll
        for (int j = 0; j < 8; j++) { s[j] = 0.f; s2[j] = 0.f; }
    }
    #pragma unroll
    for (int mt = 0; mt < 4; mt++) {
        #pragma unroll
        for (int nt = 0; nt < 4; nt++) {
            int col = bn + wn * 32 + nt * 8 + tig * 2;
            float b0 = __ldg(&bias[col]), b1 = __ldg(&bias[col + 1]);
            #pragma unroll
            for (int half = 0; half < 2; half++) {
                int r = bm + wm * 64 + mt * 16 + gid + half * 8;
                if (r >= NN) continue;
                float v0 = c[mt][nt][half * 2 + 0] + b0;
                float v1 = c[mt][nt][half * 2 + 1] + b1;
                if (MODE == 0) {
                    v0 = fmaxf(v0, 0.f); v1 = fmaxf(v1, 0.f);
                    __nv_bfloat16 h0 = __float2bfloat16(v0), h1 = __float2bfloat16(v1);
                    __nv_bfloat16 l0 = __float2bfloat16(v0 - __bfloat162float(h0));
                    __nv_bfloat16 l1 = __float2bfloat16(v1 - __bfloat162float(h1));
                    *(__nv_bfloat162*)(Ohi + (size_t)r * 256 + col) = __halves2bfloat162(h0, h1);
                    *(__nv_bfloat162*)(Olo + (size_t)r * 256 + col) = __halves2bfloat162(l0, l1);
                } else {
                    *(float2*)(Of + (size_t)r * 256 + col) = make_float2(v0, v1);
                    s[nt * 2 + 0] += v0; s2[nt * 2 + 0] += v0 * v0;
                    s[nt * 2 + 1] += v1; s2[nt * 2 + 1] += v1 * v1;
                }
            }
        }
    }
    if (MODE == 1) {
        #pragma unroll
        for (int j = 0; j < 8; j++) {
            #pragma unroll
            for (int off = 4; off < 32; off <<= 1) {
                s[j]  += __shfl_xor_sync(0xffffffffu, s[j], off);
                s2[j] += __shfl_xor_sync(0xffffffffu, s2[j], off);
            }
        }
        float* ss  = (float*)smem;          // [2][128]
        float* ssq = ss + 256;              // [2][128]
        if (gid == 0) {
            #pragma unroll
            for (int nt = 0; nt < 4; nt++) {
                #pragma unroll
                for (int q = 0; q < 2; q++) {
                    int cl = wn * 32 + nt * 8 + tig * 2 + q;
                    ss[wm * 128 + cl]  = s[nt * 2 + q];
                    ssq[wm * 128 + cl] = s2[nt * 2 + q];
                }
            }
        }
        __syncthreads();
        if (tid < 128) {
            int slot = blockIdx.y * 256 + bn + tid;
            d_psum[slot] = ss[tid] + ss[128 + tid];
            d_psq[slot]  = ssq[tid] + ssq[128 + tid];
        }
        // last-CTA BN finalize (deterministic fixed-order reduce by one block)
        __shared__ int isLast;
        __threadfence();
        __syncthreads();
        if (tid == 0) isLast = (atomicAdd(&d_bn_ctr, 1) == 2 * NMB - 1);
        __syncthreads();
        if (isLast) {
            __threadfence();
            float fs = 0.f, fs2 = 0.f;
            for (int blk = 0; blk < NMB; blk++) {
                fs  += d_psum[blk * HID + tid];
                fs2 += d_psq[blk * HID + tid];
            }
            float mu = fs / (float)NN;
            float var = fs2 / (float)NN - mu * mu;
            float sc = __ldg(&bng[tid]) * rsqrtf(var + 1e-5f);
            d_scale[tid] = sc;
            d_shift[tid] = __ldg(&bnb[tid]) - mu * sc;
            if (tid == 0) d_bn_ctr = 0;
        }
    }
}

// ---------------- BatchNorm apply ----------------
__global__ void k_bn_apply() {
    int idx = blockIdx.x * blockDim.x + threadIdx.x;   // float4 index
    if (idx >= NN * 64) return;
    int c4 = idx & 63;
    float4 z = *(const float4*)(d_z + idx * 4);
    float4 h = *(const float4*)(d_h + idx * 4);
    float4 sc = *(const float4*)(d_scale + c4 * 4);
    float4 sh = *(const float4*)(d_shift + c4 * 4);
    h.x += fmaxf(z.x * sc.x + sh.x, 0.f);
    h.y += fmaxf(z.y * sc.y + sh.y, 0.f);
    h.z += fmaxf(z.z * sc.z + sh.z, 0.f);
    h.w += fmaxf(z.w * sc.w + sh.w, 0.f);
    *(float4*)(d_h + idx * 4) = h;
}

// ---------------- graph pooling (fused with layer-3 BN apply) ----------------
__global__ void k_gbounds(const int* __restrict__ batch) {
    int g = blockIdx.x * blockDim.x + threadIdx.x;
    if (g > NG) return;
    if (g == NG) { d_gstart[NG] = NN; return; }
    int lo = 0, hi = NN;
    while (lo < hi) {
        int mid = (lo + hi) >> 1;
        if (batch[mid] < g) lo = mid + 1; else hi = mid;
    }
    d_gstart[g] = lo;
}
__global__ void k_pool_bn() {
    int g = blockIdx.x, c = threadIdx.x;
    int s0 = d_gstart[g], s1 = d_gstart[g + 1];
    float sc = d_scale[c], sh = d_shift[c];
    float sum = 0.f;
    float mx = -INFINITY;
    for (int n = s0; n < s1; n++) {
        float hn = fmaxf(d_z[n * HID + c] * sc + sh, 0.f) + d_h[n * HID + c];
        sum += hn;
        mx = fmaxf(mx, hn);
    }
    float cntf = (float)(s1 - s0);
    float mean = sum / fmaxf(cntf, 1.f);
    d_gfeat[g * 768 + c] = mean;
    d_gfeat[g * 768 + 256 + c] = sum;
    d_gfeat[g * 768 + 512 + c] = mx;
}

// ---------------- fused head: 3 layers in one kernel, 8 graphs per block ----------------
__global__ __launch_bounds__(256)
void k_head(const float* __restrict__ W1, const float* __restrict__ b1,
            const float* __restrict__ W2, const float* __restrict__ b2,
            const float* __restrict__ W3, const float* __restrict__ b3,
            float* __restrict__ out) {
    __shared__ float gs[8][768];
    __shared__ float h1s[8][256];
    __shared__ float h2s[8][128];
    int tid = threadIdx.x;
    int g0 = blockIdx.x * 8;
    for (int j = 0; j < 8; j++)
        for (int idx = tid; idx < 768; idx += 256)
            gs[j][idx] = d_gfeat[(g0 + j) * 768 + idx];
    __syncthreads();
    // stage 1: 768 -> 256, relu
    {
        int c = tid;
        float acc[8];
        float bv = __ldg(&b1[c]);
        #pragma unroll
        for (int j = 0; j < 8; j++) acc[j] = bv;
        for (int k = 0; k < 768; k++) {
            float w = __ldg(&W1[k * 256 + c]);
            #pragma unroll
            for (int j = 0; j < 8; j++) acc[j] = fmaf(gs[j][k], w, acc[j]);
        }
        #pragma unroll
        for (int j = 0; j < 8; j++) h1s[j][c] = fmaxf(acc[j], 0.f);
    }
    __syncthreads();
    // stage 2: 256 -> 128, relu; 256 threads = (2 graph-halves) x 128 cols
    {
        int c = tid & 127, jh = tid >> 7;     // jh in {0,1}: graphs [0..3] / [4..7]
        float acc[4];
        float bv = __ldg(&b2[c]);
        #pragma unroll
        for (int j = 0; j < 4; j++) acc[j] = bv;
        for (int k = 0; k < 256; k++) {
            float w = __ldg(&W2[k * 128 + c]);
            #pragma unroll
            for (int j = 0; j < 4; j++) acc[j] = fmaf(h1s[jh * 4 + j][k], w, acc[j]);
        }
        #pragma unroll
        for (int j = 0; j < 4; j++) h2s[jh * 4 + j][c] = fmaxf(acc[j], 0.f);
    }
    __syncthreads();
    // stage 3: 128 -> 1; warp w handles graph g0+w
    {
        int w = tid >> 5, lane = tid & 31;
        float s = 0.f;
        #pragma unroll
        for (int k = lane; k < 128; k += 32)
            s = fmaf(h2s[w][k], __ldg(&W3[k]), s);
        #pragma unroll
        for (int off = 16; off; off >>= 1) s += __shfl_xor_sync(0xffffffffu, s, off);
        if (lane == 0) out[g0 + w] = s + __ldg(&b3[0]);
    }
}

// ---------------- launch ----------------
extern "C" void kernel_launch(void* const* d_in, const int* in_sizes, int n_in,
                              void* d_out, int out_size) {
    const float* x      = (const float*)d_in[0];
    const int*   ei     = (const int*)d_in[1];
    const float* ea     = (const float*)d_in[2];
    const int*   batch  = (const int*)d_in[3];
    const float* enc_W  = (const float*)d_in[4];
    const float* enc_b  = (const float*)d_in[5];
    const float* edge_W = (const float*)d_in[6];
    const float* edge_b = (const float*)d_in[7];
    const float* mlp_W1 = (const float*)d_in[8];
    const float* mlp_b1 = (const float*)d_in[9];
    const float* mlp_W2 = (const float*)d_in[10];
    const float* mlp_b2 = (const float*)d_in[11];
    const float* bn_g   = (const float*)d_in[12];
    const float* bn_b   = (const float*)d_in[13];
    const float* hW1    = (const float*)d_in[14];
    const float* hb1    = (const float*)d_in[15];
    const float* hW2    = (const float*)d_in[16];
    const float* hb2    = (const float*)d_in[17];
    const float* hW3    = (const float*)d_in[18];
    const float* hb3    = (const float*)d_in[19];
    float* out = (float*)d_out;

    static __nv_bfloat16 *p_zhi = nullptr, *p_zlo = nullptr, *p_thi = nullptr,
                         *p_tlo = nullptr, *p_Wc = nullptr;
    static float* p_z = nullptr;
    static int* p_cnt = nullptr;
    if (!p_zhi) {
        cudaGetSymbolAddress((void**)&p_zhi, d_zhi);
        cudaGetSymbolAddress((void**)&p_zlo, d_zlo);
        cudaGetSymbolAddress((void**)&p_thi, d_thi);
        cudaGetSymbolAddress((void**)&p_tlo, d_tlo);
        cudaGetSymbolAddress((void**)&p_Wc, d_Wc);
        cudaGetSymbolAddress((void**)&p_z, d_z);
        cudaGetSymbolAddress((void**)&p_cnt, d_cnt);
        cudaFuncSetAttribute(k_mma_gemm<0>, cudaFuncAttributeMaxDynamicSharedMemorySize, 2 * SM_BUF);
        cudaFuncSetAttribute(k_mma_gemm<1>, cudaFuncAttributeMaxDynamicSharedMemorySize, 2 * SM_BUF);
    }

    // weight conversion (deterministic, every call)
    k_convW<<<(NLAYER * 2 * HID * HID + 255) / 256, 256>>>(mlp_W1, mlp_W2);

    // CSR build (deterministic)
    cudaMemsetAsync(p_cnt, 0, NN * sizeof(int));
    k_count<<<(NE + 255) / 256, 256>>>(ei);
    k_bsum<<<NSB, 256>>>();
    k_bscan<<<1, 256>>>();
    k_badd<<<NSB, 256>>>();
    k_scatter<<<(NE + 255) / 256, 256>>>(ei);
    k_sortrows<<<(NN + 255) / 256, 256>>>();

    // encoder
    k_encoder<<<(NN + ENC_NPB - 1) / ENC_NPB, 256>>>(x, enc_W, enc_b);

    dim3 gemm_grid(2, NMB);   // (N/128, M/128)
    for (int l = 0; l < NLAYER; l++) {
        k_aggregate<<<(NN + 7) / 8, 256>>>(ei, ea, edge_W + l * EDGE_DIM * HID,
                                           edge_b + l * HID);
        const __nv_bfloat16* W1c = p_Wc + (size_t)(l * 2 + 0) * 2 * 65536;
        const __nv_bfloat16* W2c = p_Wc + (size_t)(l * 2 + 1) * 2 * 65536;
        k_mma_gemm<0><<<gemm_grid, 256, 2 * SM_BUF>>>(p_zhi, p_zlo, W1c, mlp_b1 + l * HID,
                                                      p_thi, p_tlo, nullptr, nullptr, nullptr);
        k_mma_gemm<1><<<gemm_grid, 256, 2 * SM_BUF>>>(p_thi, p_tlo, W2c, mlp_b2 + l * HID,
                                                      nullptr, nullptr, p_z,
                                                      bn_g + l * HID, bn_b + l * HID);
        if (l < NLAYER - 1)
            k_bn_apply<<<(NN * 64 + 255) / 256, 256>>>();
    }

    // pooling (fused with last BN apply) + fused head
    k_gbounds<<<(NG + 256) / 256, 256>>>(batch);
    k_pool_bn<<<NG, 256>>>();
    k_head<<<NG / 8, 256>>>(hW1, hb1, hW2, hb2, hW3, hb3, out);
}